// round 4
// baseline (speedup 1.0000x reference)
#include <cuda_runtime.h>

#define LAM 0.95f
#define ETA 0.5f
#define B_SZ 128
#define D_SZ 1024
#define VEC_PER_ROW (D_SZ / 4)   // 256
#define ROWS_PER_GRP 4
#define GRPS_PER_BLK 2           // 8 rows per block, 4-row pipelined groups

// out[b,i,j] = LAM*A[b,i,j] + ETA*h[b,i]*h[b,j]
// One block = 8 consecutive rows of one batch, processed as 2 groups of 4.
// Per group: 4 front-batched streaming loads (MLP=4, like the R2 winner),
// compute, 4 streaming stores. Only 4 float4 live at once -> regs ~36,
// occupancy stays high. hj loaded once per block.
__global__ void __launch_bounds__(256) fastweight_kernel(
    const float4* __restrict__ A,
    const float* __restrict__ h,
    float4* __restrict__ out)
{
    int blk = blockIdx.x;
    int b  = blk >> 7;                    // 128 row-octets per batch (1024/8)
    int rg = blk & 127;
    int i0 = rg * (ROWS_PER_GRP * GRPS_PER_BLK);
    int t  = threadIdx.x;                 // j4 in [0,256)

    // vec4 index fits in 32 bits (max 33.5M)
    int base = (b * D_SZ + i0) * VEC_PER_ROW + t;

    const float4 hj = __ldg(((const float4*)h) + b * VEC_PER_ROW + t);
    const float* hrow = h + b * D_SZ + i0;

#pragma unroll
    for (int g = 0; g < GRPS_PER_BLK; g++) {
        int gbase = base + g * (ROWS_PER_GRP * VEC_PER_ROW);

        // Front-batch the 4 streaming loads
        float4 a0 = __ldcs(A + gbase + 0 * VEC_PER_ROW);
        float4 a1 = __ldcs(A + gbase + 1 * VEC_PER_ROW);
        float4 a2 = __ldcs(A + gbase + 2 * VEC_PER_ROW);
        float4 a3 = __ldcs(A + gbase + 3 * VEC_PER_ROW);

        float hi0 = __ldg(hrow + g * ROWS_PER_GRP + 0) * ETA;
        float hi1 = __ldg(hrow + g * ROWS_PER_GRP + 1) * ETA;
        float hi2 = __ldg(hrow + g * ROWS_PER_GRP + 2) * ETA;
        float hi3 = __ldg(hrow + g * ROWS_PER_GRP + 3) * ETA;

        float4 v;
        v.x = fmaf(hi0, hj.x, a0.x * LAM);
        v.y = fmaf(hi0, hj.y, a0.y * LAM);
        v.z = fmaf(hi0, hj.z, a0.z * LAM);
        v.w = fmaf(hi0, hj.w, a0.w * LAM);
        __stcs(out + gbase + 0 * VEC_PER_ROW, v);

        v.x = fmaf(hi1, hj.x, a1.x * LAM);
        v.y = fmaf(hi1, hj.y, a1.y * LAM);
        v.z = fmaf(hi1, hj.z, a1.z * LAM);
        v.w = fmaf(hi1, hj.w, a1.w * LAM);
        __stcs(out + gbase + 1 * VEC_PER_ROW, v);

        v.x = fmaf(hi2, hj.x, a2.x * LAM);
        v.y = fmaf(hi2, hj.y, a2.y * LAM);
        v.z = fmaf(hi2, hj.z, a2.z * LAM);
        v.w = fmaf(hi2, hj.w, a2.w * LAM);
        __stcs(out + gbase + 2 * VEC_PER_ROW, v);

        v.x = fmaf(hi3, hj.x, a3.x * LAM);
        v.y = fmaf(hi3, hj.y, a3.y * LAM);
        v.z = fmaf(hi3, hj.z, a3.z * LAM);
        v.w = fmaf(hi3, hj.w, a3.w * LAM);
        __stcs(out + gbase + 3 * VEC_PER_ROW, v);
    }
}

extern "C" void kernel_launch(void* const* d_in, const int* in_sizes, int n_in,
                              void* d_out, int out_size) {
    const float4* A = (const float4*)d_in[0];
    const float*  h = (const float*)d_in[1];
    float4* out = (float4*)d_out;

    // grid = B * (D / 8) = 128 * 128 = 16384 blocks
    int blocks = B_SZ * (D_SZ / (ROWS_PER_GRP * GRPS_PER_BLK));
    fastweight_kernel<<<blocks, 256>>>(A, h, out);
}

// round 5
// speedup vs baseline: 1.0024x; 1.0024x over previous
#include <cuda_runtime.h>

#define LAM 0.95f
#define ETA 0.5f
#define B_SZ 128
#define D_SZ 1024
#define VEC_PER_ROW (D_SZ / 4)   // 256
#define ROWS_PER_BLK 4

// out[b,i,j] = LAM*A[b,i,j] + ETA*h[b,i]*h[b,j]
// R2 winning shape: one block = 4 consecutive rows of one batch, 256 threads,
// thread t owns column-group j4=t for all 4 rows. hj loaded once, 4 A loads
// front-batched (MLP=4), occ ~82%, 32768 independent blocks.
// R5 change: stores use write-through (__stwt) instead of evict-first —
// out is never re-read, so skip L2 allocation on the write path.
__device__ __forceinline__ void stwt4(float4* p, float4 v) {
    asm volatile("st.global.wt.v4.f32 [%0], {%1,%2,%3,%4};"
                 :: "l"(p), "f"(v.x), "f"(v.y), "f"(v.z), "f"(v.w) : "memory");
}

__global__ void __launch_bounds__(256) fastweight_kernel(
    const float4* __restrict__ A,
    const float* __restrict__ h,
    float4* __restrict__ out)
{
    int blk = blockIdx.x;
    int b  = blk >> 8;                    // 256 row-groups per batch (1024/4)
    int rg = blk & 255;
    int i0 = rg * ROWS_PER_BLK;
    int t  = threadIdx.x;                 // j4 in [0,256)

    int base = (b * D_SZ + i0) * VEC_PER_ROW + t;   // fits in 32 bits

    const float4 hj = __ldg(((const float4*)h) + b * VEC_PER_ROW + t);

    const float* hrow = h + b * D_SZ + i0;
    float hi0 = __ldg(hrow + 0) * ETA;
    float hi1 = __ldg(hrow + 1) * ETA;
    float hi2 = __ldg(hrow + 2) * ETA;
    float hi3 = __ldg(hrow + 3) * ETA;

    // Front-batch the 4 streaming loads (MLP=4)
    float4 a0 = __ldcs(A + base + 0 * VEC_PER_ROW);
    float4 a1 = __ldcs(A + base + 1 * VEC_PER_ROW);
    float4 a2 = __ldcs(A + base + 2 * VEC_PER_ROW);
    float4 a3 = __ldcs(A + base + 3 * VEC_PER_ROW);

    float4 r;
    r.x = fmaf(hi0, hj.x, a0.x * LAM);
    r.y = fmaf(hi0, hj.y, a0.y * LAM);
    r.z = fmaf(hi0, hj.z, a0.z * LAM);
    r.w = fmaf(hi0, hj.w, a0.w * LAM);
    stwt4(out + base + 0 * VEC_PER_ROW, r);

    r.x = fmaf(hi1, hj.x, a1.x * LAM);
    r.y = fmaf(hi1, hj.y, a1.y * LAM);
    r.z = fmaf(hi1, hj.z, a1.z * LAM);
    r.w = fmaf(hi1, hj.w, a1.w * LAM);
    stwt4(out + base + 1 * VEC_PER_ROW, r);

    r.x = fmaf(hi2, hj.x, a2.x * LAM);
    r.y = fmaf(hi2, hj.y, a2.y * LAM);
    r.z = fmaf(hi2, hj.z, a2.z * LAM);
    r.w = fmaf(hi2, hj.w, a2.w * LAM);
    stwt4(out + base + 2 * VEC_PER_ROW, r);

    r.x = fmaf(hi3, hj.x, a3.x * LAM);
    r.y = fmaf(hi3, hj.y, a3.y * LAM);
    r.z = fmaf(hi3, hj.z, a3.z * LAM);
    r.w = fmaf(hi3, hj.w, a3.w * LAM);
    stwt4(out + base + 3 * VEC_PER_ROW, r);
}

extern "C" void kernel_launch(void* const* d_in, const int* in_sizes, int n_in,
                              void* d_out, int out_size) {
    const float4* A = (const float4*)d_in[0];
    const float*  h = (const float*)d_in[1];
    float4* out = (float4*)d_out;

    // grid = B * (D / 4) = 128 * 256 = 32768 blocks
    int blocks = B_SZ * (D_SZ / ROWS_PER_BLK);
    fastweight_kernel<<<blocks, 256>>>(A, h, out);
}

// round 6
// speedup vs baseline: 1.0037x; 1.0012x over previous
#include <cuda_runtime.h>

#define LAM 0.95f
#define ETA 0.5f
#define B_SZ 128
#define D_SZ 1024
#define VEC_PER_ROW (D_SZ / 4)   // 256
#define ROWS_PER_BLK 4

// out[b,i,j] = LAM*A[b,i,j] + ETA*h[b,i]*h[b,j]
// R2 winning shape: one block = 4 consecutive rows of one batch, 256 threads,
// thread t owns column-group j4=t for all 4 rows. hj loaded once, 4 A loads
// front-batched (MLP=4), 32768 independent blocks, occ ~82%.
// R6 change: default-cached loads for A (allow L2 promotion/prefetch on the
// streaming read); stores stay evict-first.
__global__ void __launch_bounds__(256) fastweight_kernel(
    const float4* __restrict__ A,
    const float* __restrict__ h,
    float4* __restrict__ out)
{
    int blk = blockIdx.x;
    int b  = blk >> 8;                    // 256 row-groups per batch (1024/4)
    int rg = blk & 255;
    int i0 = rg * ROWS_PER_BLK;
    int t  = threadIdx.x;                 // j4 in [0,256)

    int base = (b * D_SZ + i0) * VEC_PER_ROW + t;   // fits in 32 bits

    const float4 hj = __ldg(((const float4*)h) + b * VEC_PER_ROW + t);

    const float* hrow = h + b * D_SZ + i0;
    float hi0 = __ldg(hrow + 0) * ETA;
    float hi1 = __ldg(hrow + 1) * ETA;
    float hi2 = __ldg(hrow + 2) * ETA;
    float hi3 = __ldg(hrow + 3) * ETA;

    // Front-batch the 4 loads (MLP=4), default cache policy
    float4 a0 = A[base + 0 * VEC_PER_ROW];
    float4 a1 = A[base + 1 * VEC_PER_ROW];
    float4 a2 = A[base + 2 * VEC_PER_ROW];
    float4 a3 = A[base + 3 * VEC_PER_ROW];

    float4 r;
    r.x = fmaf(hi0, hj.x, a0.x * LAM);
    r.y = fmaf(hi0, hj.y, a0.y * LAM);
    r.z = fmaf(hi0, hj.z, a0.z * LAM);
    r.w = fmaf(hi0, hj.w, a0.w * LAM);
    __stcs(out + base + 0 * VEC_PER_ROW, r);

    r.x = fmaf(hi1, hj.x, a1.x * LAM);
    r.y = fmaf(hi1, hj.y, a1.y * LAM);
    r.z = fmaf(hi1, hj.z, a1.z * LAM);
    r.w = fmaf(hi1, hj.w, a1.w * LAM);
    __stcs(out + base + 1 * VEC_PER_ROW, r);

    r.x = fmaf(hi2, hj.x, a2.x * LAM);
    r.y = fmaf(hi2, hj.y, a2.y * LAM);
    r.z = fmaf(hi2, hj.z, a2.z * LAM);
    r.w = fmaf(hi2, hj.w, a2.w * LAM);
    __stcs(out + base + 2 * VEC_PER_ROW, r);

    r.x = fmaf(hi3, hj.x, a3.x * LAM);
    r.y = fmaf(hi3, hj.y, a3.y * LAM);
    r.z = fmaf(hi3, hj.z, a3.z * LAM);
    r.w = fmaf(hi3, hj.w, a3.w * LAM);
    __stcs(out + base + 3 * VEC_PER_ROW, r);
}

extern "C" void kernel_launch(void* const* d_in, const int* in_sizes, int n_in,
                              void* d_out, int out_size) {
    const float4* A = (const float4*)d_in[0];
    const float*  h = (const float*)d_in[1];
    float4* out = (float4*)d_out;

    // grid = B * (D / 4) = 128 * 256 = 32768 blocks
    int blocks = B_SZ * (D_SZ / ROWS_PER_BLK);
    fastweight_kernel<<<blocks, 256>>>(A, h, out);
}

// round 7
// speedup vs baseline: 1.0133x; 1.0096x over previous
#include <cuda_runtime.h>

#define LAM 0.95f
#define ETA 0.5f
#define B_SZ 128
#define D_SZ 1024
#define VEC_PER_ROW (D_SZ / 4)   // 256
#define ROWS_PER_BLK 4

// out[b,i,j] = LAM*A[b,i,j] + ETA*h[b,i]*h[b,j]
// Final configuration (R2 winner, confirmed across 5 variant rounds):
// - one block = 4 consecutive rows of one batch; 256 threads; thread t owns
//   column-group j4 = t for all 4 rows (hj loaded once per thread)
// - 4 A loads front-batched (MLP=4), evict-first on both streams
// - 32768 independent blocks, occ ~82%, regs 32
// Measured: ~156 us wall, 6.85 TB/s (86% of HBM spec) — read/write-turnaround
// bound; issue=10%, fma=6%: no SM-side headroom remains.
__global__ void __launch_bounds__(256) fastweight_kernel(
    const float4* __restrict__ A,
    const float* __restrict__ h,
    float4* __restrict__ out)
{
    int blk = blockIdx.x;
    int b  = blk >> 8;                    // 256 row-groups per batch (1024/4)
    int rg = blk & 255;
    int i0 = rg * ROWS_PER_BLK;
    int t  = threadIdx.x;                 // j4 in [0,256)

    int base = (b * D_SZ + i0) * VEC_PER_ROW + t;   // fits in 32 bits

    const float4 hj = __ldg(((const float4*)h) + b * VEC_PER_ROW + t);

    const float* hrow = h + b * D_SZ + i0;
    float hi0 = __ldg(hrow + 0) * ETA;
    float hi1 = __ldg(hrow + 1) * ETA;
    float hi2 = __ldg(hrow + 2) * ETA;
    float hi3 = __ldg(hrow + 3) * ETA;

    // Front-batch the 4 streaming loads (MLP=4)
    float4 a0 = __ldcs(A + base + 0 * VEC_PER_ROW);
    float4 a1 = __ldcs(A + base + 1 * VEC_PER_ROW);
    float4 a2 = __ldcs(A + base + 2 * VEC_PER_ROW);
    float4 a3 = __ldcs(A + base + 3 * VEC_PER_ROW);

    float4 r;
    r.x = fmaf(hi0, hj.x, a0.x * LAM);
    r.y = fmaf(hi0, hj.y, a0.y * LAM);
    r.z = fmaf(hi0, hj.z, a0.z * LAM);
    r.w = fmaf(hi0, hj.w, a0.w * LAM);
    __stcs(out + base + 0 * VEC_PER_ROW, r);

    r.x = fmaf(hi1, hj.x, a1.x * LAM);
    r.y = fmaf(hi1, hj.y, a1.y * LAM);
    r.z = fmaf(hi1, hj.z, a1.z * LAM);
    r.w = fmaf(hi1, hj.w, a1.w * LAM);
    __stcs(out + base + 1 * VEC_PER_ROW, r);

    r.x = fmaf(hi2, hj.x, a2.x * LAM);
    r.y = fmaf(hi2, hj.y, a2.y * LAM);
    r.z = fmaf(hi2, hj.z, a2.z * LAM);
    r.w = fmaf(hi2, hj.w, a2.w * LAM);
    __stcs(out + base + 2 * VEC_PER_ROW, r);

    r.x = fmaf(hi3, hj.x, a3.x * LAM);
    r.y = fmaf(hi3, hj.y, a3.y * LAM);
    r.z = fmaf(hi3, hj.z, a3.z * LAM);
    r.w = fmaf(hi3, hj.w, a3.w * LAM);
    __stcs(out + base + 3 * VEC_PER_ROW, r);
}

extern "C" void kernel_launch(void* const* d_in, const int* in_sizes, int n_in,
                              void* d_out, int out_size) {
    const float4* A = (const float4*)d_in[0];
    const float*  h = (const float*)d_in[1];
    float4* out = (float4*)d_out;

    // grid = B * (D / 4) = 128 * 256 = 32768 blocks
    int blocks = B_SZ * (D_SZ / ROWS_PER_BLK);
    fastweight_kernel<<<blocks, 256>>>(A, h, out);
}